// round 4
// baseline (speedup 1.0000x reference)
#include <cuda_runtime.h>
#include <stdint.h>

// ChannelPair2D: out[p, k] = x[p, i_k] * x[p, j_k], (i,j) i<j row-major triu.
// C=64 -> 2016 pairs, 65536 pixels. HBM-write-bound (~504 MiB out).
//
// R3: quad descriptors live in REGISTERS (each thread owns quads tid and
// tid+256 for all PPB pixels) -> no shared table, no per-iter unpack.
// Pixel loop fully unrolled so LDS/STG use immediate offsets.

#define C_CH    64
#define NPAIR   2016
#define NQ      504       // NPAIR/4 quads
#define TPB     256
#define PPB     8         // pixels per block

__global__ __launch_bounds__(TPB)
void channelpair_kernel(const float* __restrict__ x,
                        float* __restrict__ out,
                        int npix) {
    // Shifted replicas: Bf[(s*PPB + p)*64 + c] = x_p[c+s], s=0..3.
    // Fast path loads x[j..j+3] as one aligned LDS.128 at s=j&3, c=j&~3.
    __shared__ __align__(16) float Bf[4 * PPB * C_CH];   // 8 KB

    const int tid  = threadIdx.x;
    const int pix0 = blockIdx.x * PPB;

    // ---- Per-thread quad descriptors (computed once, kept in registers) ----
    int  d_fast[2];    // 1 = run-interior quad (single i, consecutive j)
    int  d_xi[2];      // float index of x[i] in Bf (s=0 plane)
    int  d_sv[2];      // float index of the shifted j-vector
    uint2 d_pk[2];     // packed (i,j) bytes for the boundary path

    #pragma unroll
    for (int w = 0; w < 2; ++w) {
        const int q = tid + w * TPB;    // q < NQ guaranteed for w=0; w=1 may be >= NQ
        const int k = 4 * q;
        int i = (int)((127.0f - sqrtf(16129.0f - 8.0f * (float)k)) * 0.5f);
        i = (i < 0) ? 0 : ((i > 62) ? 62 : i);
        while (i > 0  && k <  i * (127 - i) / 2)       --i;
        while (i < 62 && k >= (i + 1) * (126 - i) / 2) ++i;
        const int j = i + 1 + (k - i * (127 - i) / 2);

        d_fast[w] = (j + 3 <= 63);
        d_xi[w]   = i;
        d_sv[w]   = (j & 3) * (PPB * C_CH) + (j & ~3);

        unsigned a, b;
        int ii = i, jj = j;
        a  = (unsigned)ii | ((unsigned)jj << 8);
        if (++jj > 63) { ++ii; jj = ii + 1; }
        a |= ((unsigned)ii << 16) | ((unsigned)jj << 24);
        if (++jj > 63) { ++ii; jj = ii + 1; }
        b  = (unsigned)ii | ((unsigned)jj << 8);
        if (++jj > 63) { ++ii; jj = ii + 1; }
        b |= ((unsigned)ii << 16) | ((unsigned)jj << 24);
        d_pk[w] = make_uint2(a, b);
    }

    // ---- Load PPB pixel vectors into plane s=0 (coalesced float4) ----
    {
        float4* dst = (float4*)Bf;
        const float4* src = (const float4*)(x + (size_t)pix0 * C_CH);
        for (int t = tid; t < PPB * (C_CH / 4); t += TPB) {
            const int pix = pix0 + t / (C_CH / 4);
            dst[t] = (pix < npix) ? src[t] : make_float4(0.f, 0.f, 0.f, 0.f);
        }
    }
    __syncthreads();

    // ---- Build shifted replicas s=1..3 (conflict-free) ----
    for (int t = tid; t < 3 * PPB * C_CH; t += TPB) {
        const int s = 1 + t / (PPB * C_CH);
        const int r = t % (PPB * C_CH);
        const int c = r % C_CH;
        const int src_c = (c + s > 63) ? 63 : (c + s);
        Bf[s * (PPB * C_CH) + (r - c) + c] = Bf[(r - c) + src_c];
    }
    __syncthreads();

    // ---- Main loop: 2 quads/thread x PPB pixels, immediate-offset LDS/STG ----
    const bool full = (pix0 + PPB <= npix);
    float4* __restrict__ out4 = (float4*)(out + (size_t)pix0 * NPAIR);

    #pragma unroll
    for (int w = 0; w < 2; ++w) {
        const int q = tid + w * TPB;
        if (q >= NQ) continue;
        float4* __restrict__ o4 = out4 + q;

        if (d_fast[w]) {
            const float* xiP = Bf + d_xi[w];
            const float* svP = Bf + d_sv[w];
            if (full) {
                #pragma unroll
                for (int p = 0; p < PPB; ++p) {
                    const float  xi = xiP[p * C_CH];
                    const float4 v  = *(const float4*)(svP + p * C_CH);
                    float4 r;
                    r.x = xi * v.x; r.y = xi * v.y;
                    r.z = xi * v.z; r.w = xi * v.w;
                    o4[p * NQ] = r;
                }
            } else {
                for (int p = 0; p < PPB && pix0 + p < npix; ++p) {
                    const float  xi = xiP[p * C_CH];
                    const float4 v  = *(const float4*)(svP + p * C_CH);
                    float4 r;
                    r.x = xi * v.x; r.y = xi * v.y;
                    r.z = xi * v.z; r.w = xi * v.w;
                    o4[p * NQ] = r;
                }
            }
        } else {
            const uint2 t = d_pk[w];
            const int i0 = t.x & 255,          j0 = (t.x >> 8) & 255;
            const int i1 = (t.x >> 16) & 255,  j1 = (t.x >> 24) & 255;
            const int i2 = t.y & 255,          j2 = (t.y >> 8) & 255;
            const int i3 = (t.y >> 16) & 255,  j3 = (t.y >> 24) & 255;
            if (full) {
                #pragma unroll
                for (int p = 0; p < PPB; ++p) {
                    const float* xv = Bf + p * C_CH;
                    float4 r;
                    r.x = xv[i0] * xv[j0];
                    r.y = xv[i1] * xv[j1];
                    r.z = xv[i2] * xv[j2];
                    r.w = xv[i3] * xv[j3];
                    o4[p * NQ] = r;
                }
            } else {
                for (int p = 0; p < PPB && pix0 + p < npix; ++p) {
                    const float* xv = Bf + p * C_CH;
                    float4 r;
                    r.x = xv[i0] * xv[j0];
                    r.y = xv[i1] * xv[j1];
                    r.z = xv[i2] * xv[j2];
                    r.w = xv[i3] * xv[j3];
                    o4[p * NQ] = r;
                }
            }
        }
    }
}

extern "C" void kernel_launch(void* const* d_in, const int* in_sizes, int n_in,
                              void* d_out, int out_size) {
    const float* x = (const float*)d_in[0];
    float* out = (float*)d_out;

    const int npix = in_sizes[0] / C_CH;          // 65536
    const int nblk = (npix + PPB - 1) / PPB;      // 8192

    channelpair_kernel<<<nblk, TPB>>>(x, out, npix);
}